// round 9
// baseline (speedup 1.0000x reference)
#include <cuda_runtime.h>
#include <cuda_bf16.h>
#include <math.h>

#define N_PROP   65536
#define N_GT     64
#define NCLS     81
#define TOTAL    512
#define MAX_POS  128

// ---- K1: 4 threads per proposal ----
#define K1_TPB   512
#define K1_NBLK  512            // 65536*4/512

// ---- K2: 1 thread per proposal-group slot ----
#define K2_TPB   256
#define NGRP2    256            // groups of 256 proposals
#define NWARP2   (K2_TPB / 32)

// -------- device scratch --------
__device__ int   g_res[N_PROP];       // f | (gt << 2)
__device__ int   g_grp_pos[NGRP2];    // per-256-prop group counts (atomic, deterministic)
__device__ int   g_grp_neg[NGRP2];
__device__ int   g_pos_list[TOTAL];   // packed (gt<<16)|i
__device__ int   g_neg_list[TOTAL];
__device__ int   g_non_list[TOTAL];
__device__ float g_ce[TOTAL];
__device__ float g_rg[TOTAL];
__device__ int          g_cntB[32];
__device__ volatile int g_genB[32];
__device__ int          g_done;

__device__ __forceinline__ float sl1(float d) {
    float ad = fabsf(d);
    return (ad < 1.0f) ? (0.5f * d * d) : (ad - 0.5f);
}

// ================= K1: IoU + classify =================
__global__ void __launch_bounds__(K1_TPB)
k_iou(const float* __restrict__ props, const float* __restrict__ gts) {
    __shared__ float4 sg[N_GT];
    __shared__ float  sS[N_GT];      // ga + 1e-8 (comparison fold)
    __shared__ float  sga[N_GT];     // raw ga (exact final union)
    __shared__ int    wcp[16], wcn[16];

    const int t = threadIdx.x, bid = blockIdx.x;
    const int warp = t >> 5, lane = t & 31, q = t & 3;
    const unsigned full = 0xffffffffu;

    if (t < N_GT) {
        float4 g = ((const float4*)gts)[t];
        float ga = (g.z - g.x) * (g.w - g.y);
        sg[t] = g; sga[t] = ga; sS[t] = ga + 1e-8f;
    }
    __syncthreads();

    const int i = (bid * K1_TPB + t) >> 2;      // proposal index (4 lanes share)
    const float4 p = ((const float4*)props)[i];
    const float pa = (p.z - p.x) * (p.w - p.y);

    // two independent chains over this quad-lane's 16 gts
    const int j0 = q * 16;
    float biA, bSA, biB, bSB; int bjA, bjB;
    {
        float4 g = sg[j0];
        float ix = fmaxf(fminf(p.z, g.z) - fmaxf(p.x, g.x), 0.f);
        float iy = fmaxf(fminf(p.w, g.w) - fmaxf(p.y, g.y), 0.f);
        biA = ix * iy; bSA = pa + sS[j0]; bjA = j0;
        g = sg[j0 + 8];
        ix = fmaxf(fminf(p.z, g.z) - fmaxf(p.x, g.x), 0.f);
        iy = fmaxf(fminf(p.w, g.w) - fmaxf(p.y, g.y), 0.f);
        biB = ix * iy; bSB = pa + sS[j0 + 8]; bjB = j0 + 8;
    }
#pragma unroll
    for (int j = 1; j < 8; j++) {
        int jA = j0 + j, jB = j0 + 8 + j;
        float4 gA = sg[jA], gB = sg[jB];
        float SA = pa + sS[jA], SB = pa + sS[jB];
        float ixA = fmaxf(fminf(p.z, gA.z) - fmaxf(p.x, gA.x), 0.f);
        float iyA = fmaxf(fminf(p.w, gA.w) - fmaxf(p.y, gA.y), 0.f);
        float ixB = fmaxf(fminf(p.z, gB.z) - fmaxf(p.x, gB.x), 0.f);
        float iyB = fmaxf(fminf(p.w, gB.w) - fmaxf(p.y, gB.y), 0.f);
        float inA = ixA * iyA, inB = ixB * iyB;
        // iou_new > iou_best <=> in*bS > bi*S  (the -inter terms cancel exactly)
        if (inA * bSA > biA * SA) { biA = inA; bSA = SA; bjA = jA; }
        if (inB * bSB > biB * SB) { biB = inB; bSB = SB; bjB = jB; }
    }
    if (biB * bSA > biA * bSB) { biA = biB; bSA = bSB; bjA = bjB; }  // B strictly higher idx

    // quad reduce (higher-lane = higher gt range, wins only if strictly greater)
    {
        float oi = __shfl_down_sync(full, biA, 1);
        float oS = __shfl_down_sync(full, bSA, 1);
        int   oj = __shfl_down_sync(full, bjA, 1);
        if (oi * bSA > biA * oS) { biA = oi; bSA = oS; bjA = oj; }
        oi = __shfl_down_sync(full, biA, 2);
        oS = __shfl_down_sync(full, bSA, 2);
        oj = __shfl_down_sync(full, bjA, 2);
        if (oi * bSA > biA * oS) { biA = oi; bSA = oS; bjA = oj; }
    }

    int f = 0;
    if (q == 0) {
        // exact final iou in reference association order
        float u = ((pa + sga[bjA]) - biA) + 1e-8f;
        float miou = biA / u;
        f = (miou >= 0.5f) ? 1 : ((miou >= 0.1f) ? 2 : 0);
        g_res[i] = f | (bjA << 2);
    }
    unsigned bp = __ballot_sync(full, f == 1);   // non-q0 lanes have f==0
    unsigned bn = __ballot_sync(full, f == 2);
    if (lane == 0) { wcp[warp] = __popc(bp); wcn[warp] = __popc(bn); }
    __syncthreads();
    if (t == 0) {
        int cp = 0, cn = 0;
#pragma unroll
        for (int w = 0; w < 16; w++) { cp += wcp[w]; cn += wcn[w]; }
        // block covers 128 props; K2 group = 256 props -> group bid>>1
        if (cp) atomicAdd(&g_grp_pos[bid >> 1], cp);
        if (cn) atomicAdd(&g_grp_neg[bid >> 1], cn);
    }
}

// ================= K2: scan + select + loss + reduce =================
__global__ void __launch_bounds__(K2_TPB)
k_rest(const float* __restrict__ props,
       const float* __restrict__ gts,
       const int*   __restrict__ gt_labels,
       const float* __restrict__ score,
       const float* __restrict__ txty,
       float* __restrict__ out) {
    __shared__ float4 sg[N_GT];
    __shared__ int    slbl[N_GT];
    __shared__ int    wpc[NWARP2], wnc[NWARP2];
    __shared__ int    swp[NWARP2], swn[NWARP2];
    __shared__ int    ssp[NGRP2], ssn[NGRP2];
    __shared__ int    s_numpos, s_negtot, s_offp, s_offn;
    __shared__ int    s_last;
    __shared__ float  rc[NWARP2], rr[NWARP2];

    const int t = threadIdx.x, bid = blockIdx.x;
    const int warp = t >> 5, lane = t & 31;
    const unsigned full = 0xffffffffu;

    if (t < N_GT) {
        sg[t] = ((const float4*)gts)[t];
        slbl[t] = gt_labels[t];
    }

    // ---- load per-proposal result (kernel boundary = sync with K1) ----
    const int i = bid * K2_TPB + t;
    const int res = __ldcg(&g_res[i]);
    const int f  = res & 3;
    const int bj = res >> 2;

    unsigned bp = __ballot_sync(full, f == 1);
    unsigned bn = __ballot_sync(full, f == 2);
    if (lane == 0) { wpc[warp] = __popc(bp); wnc[warp] = __popc(bn); }

    // ---- scan of 256 group counts (data ready at kernel entry) ----
    {
        int ip  = __ldcg(&g_grp_pos[t]);
        int in_ = __ldcg(&g_grp_neg[t]);
#pragma unroll
        for (int o = 1; o < 32; o <<= 1) {
            int ap = __shfl_up_sync(full, ip, o);
            int an = __shfl_up_sync(full, in_, o);
            if (lane >= o) { ip += ap; in_ += an; }
        }
        if (lane == 31) { swp[warp] = ip; swn[warp] = in_; }
        __syncthreads();
        int basep = 0, basen = 0;
        for (int w = 0; w < warp; w++) { basep += swp[w]; basen += swn[w]; }
        ssp[t] = basep + ip;
        ssn[t] = basen + in_;
    }
    __syncthreads();
    if (t == 0) {
        s_offp   = (bid > 0) ? ssp[bid - 1] : 0;
        s_offn   = (bid > 0) ? ssn[bid - 1] : 0;
        s_numpos = min(ssp[NGRP2 - 1], MAX_POS);
        s_negtot = ssn[NGRP2 - 1];
    }
    __syncthreads();

    // ---- stable select -> global lists ----
    {
        int pre_p = 0, pre_n = 0;
        for (int w = 0; w < warp; w++) { pre_p += wpc[w]; pre_n += wnc[w]; }
        unsigned lm = (1u << lane) - 1u;
        int neg_before = pre_n + __popc(bn & lm);
        if (f == 1) {
            int r = s_offp + pre_p + __popc(bp & lm);
            if (r < TOTAL) g_pos_list[r] = i | (bj << 16);
        } else if (f == 2) {
            int r = s_offn + neg_before;
            if (r < TOTAL) g_neg_list[r] = i;
        }
        if (f != 2) {
            int r = (bid * K2_TPB - s_offn) + (t - neg_before);
            if (r < TOTAL) g_non_list[r] = i;
        }
    }

    // ---- ONE global barrier ----
    __syncthreads();
    if (t == 0) {
        __threadfence();
        if (atomicAdd(&g_cntB[0], 1) == NGRP2 - 1) {
            __threadfence();
            g_genB[0] = 1;
        } else {
            while (g_genB[0] == 0) { }
            __threadfence();
        }
    }
    __syncthreads();

    // ---- loss: 2 warps/block -> 512 slots ----
    if (warp < 2) {
        int slot = bid * 2 + warp;
        int num_pos = s_numpos;
        int neg_total = s_negtot;
        bool is_pos = slot < num_pos;
        int e;
        if (is_pos) e = __ldcg(&g_pos_list[slot]);
        else {
            int j = slot - num_pos;
            e = (j < neg_total) ? __ldcg(&g_neg_list[j])
                                : __ldcg(&g_non_list[j - neg_total]);
        }
        int idx = e & 0xFFFF;
        int g   = e >> 16;
        int lbl = is_pos ? slbl[g] : 0;

        const float* row = score + (size_t)idx * NCLS;
        float v0 = row[lane];
        float v1 = row[lane + 32];
        float v2 = (lane + 64 < NCLS) ? row[lane + 64] : -INFINITY;
        float m = fmaxf(fmaxf(v0, v1), v2);
#pragma unroll
        for (int o = 16; o; o >>= 1) m = fmaxf(m, __shfl_xor_sync(full, m, o));
        float s = expf(v0 - m) + expf(v1 - m) + ((lane + 64 < NCLS) ? expf(v2 - m) : 0.0f);
#pragma unroll
        for (int o = 16; o; o >>= 1) s += __shfl_xor_sync(full, s, o);

        float cand = (lbl < 32) ? v0 : ((lbl < 64) ? v1 : v2);
        float vl = __shfl_sync(full, cand, lbl & 31);

        if (lane == 0) {
            float ce = m + logf(s) - vl;
            float rg = 0.0f;
            if (is_pos) {
                float4 pp = ((const float4*)props)[idx];
                float4 gb = sg[g];
                float pw = pp.z - pp.x, ph = pp.w - pp.y;
                float pcx = pp.x + 0.5f * pw, pcy = pp.y + 0.5f * ph;
                float gw = gb.z - gb.x, gh = gb.w - gb.y;
                float gcx = gb.x + 0.5f * gw, gcy = gb.y + 0.5f * gh;
                float t0 = ((gcx - pcx) / pw) * 10.0f;
                float t1 = ((gcy - pcy) / ph) * 10.0f;
                float t2 = logf(gw / pw) * 5.0f;
                float t3 = logf(gh / ph) * 5.0f;
                float4 pv = *(const float4*)(txty + ((size_t)idx * NCLS + g) * 4);
                rg = sl1(pv.x - t0) + sl1(pv.y - t1) + sl1(pv.z - t2) + sl1(pv.w - t3);
            }
            g_ce[slot] = ce;
            g_rg[slot] = rg;
        }
    }

    // ---- last-arriving block reduces, resets state ----
    __syncthreads();
    if (t == 0) {
        __threadfence();
        s_last = (atomicAdd(&g_done, 1) == NGRP2 - 1) ? 1 : 0;
    }
    __syncthreads();
    if (s_last) {
        __threadfence();
        float c  = __ldcg(&g_ce[t])       + __ldcg(&g_ce[t + 256]);
        float r2 = __ldcg(&g_rg[t])       + __ldcg(&g_rg[t + 256]);
#pragma unroll
        for (int o = 16; o; o >>= 1) {
            c  += __shfl_xor_sync(full, c, o);
            r2 += __shfl_xor_sync(full, r2, o);
        }
        if (lane == 0) { rc[warp] = c; rr[warp] = r2; }
        __syncthreads();
        if (warp == 0) {
            float cc  = (lane < NWARP2) ? rc[lane] : 0.0f;
            float rrv = (lane < NWARP2) ? rr[lane] : 0.0f;
#pragma unroll
            for (int o = 4; o; o >>= 1) {
                cc  += __shfl_xor_sync(full, cc, o);
                rrv += __shfl_xor_sync(full, rrv, o);
            }
            if (lane == 0) {
                out[0] = cc  * (1.0f / (float)TOTAL);
                out[1] = rrv * (1.0f / (float)TOTAL);
            }
        }
        // reset shared state for next graph replay (all blocks are past use)
        g_grp_pos[t] = 0;
        g_grp_neg[t] = 0;
        if (t == 0) {
            g_cntB[0] = 0; g_genB[0] = 0; g_done = 0;
        }
    }
}

extern "C" void kernel_launch(void* const* d_in, const int* in_sizes, int n_in,
                              void* d_out, int out_size) {
    const float* props = (const float*)d_in[1];
    const float* score = (const float*)d_in[2];
    const float* txty  = (const float*)d_in[3];
    const float* gts   = (const float*)d_in[4];
    const int*   glbl  = (const int*)d_in[5];
    float* out = (float*)d_out;

    k_iou <<<K1_NBLK, K1_TPB>>>(props, gts);
    k_rest<<<NGRP2,  K2_TPB>>>(props, gts, glbl, score, txty, out);
}